// round 9
// baseline (speedup 1.0000x reference)
#include <cuda_runtime.h>
#include <cuda_bf16.h>
#include <cuda_fp16.h>
#include <math_constants.h>
#include <cstdint>

// Problem constants
#define DD 256
#define TT 4096
#define BBATCH 16
#define KK 1024
#define NTOK (BBATCH * TT)                  // 65536 tokens
#define NDATA ((size_t)BBATCH * DD * TT)    // 16777216 output data elements

// Scratch (no cudaMalloc allowed)
__device__ float          g_e2[KK];
__device__ float          g_r2[NTOK];
__device__ int            g_idx[NTOK];
__device__ double         g_loss_sum;
__device__ float          g_zt[NDATA];          // z transposed [token][d] fp32
__device__ __nv_bfloat16  g_zbf[NDATA];         // z transposed bf16
__device__ __nv_bfloat16  g_ebf[KK * DD];       // emb bf16

__device__ __forceinline__ uint32_t s2u(const void* p) {
    uint32_t a;
    asm("{ .reg .u64 t; cvta.to.shared.u64 t, %1; cvt.u32.u64 %0, t; }"
        : "=r"(a) : "l"(p));
    return a;
}

#define LDSM_X4(r0, r1, r2, r3, addr)                                          \
    asm volatile("ldmatrix.sync.aligned.m8n8.x4.shared.b16 {%0,%1,%2,%3}, [%4];" \
                 : "=r"(r0), "=r"(r1), "=r"(r2), "=r"(r3) : "r"(addr))

#define MMA16816(d, a0, a1, a2, a3, b0, b1)                                    \
    asm volatile("mma.sync.aligned.m16n8k16.row.col.f32.bf16.bf16.f32 "        \
                 "{%0,%1,%2,%3}, {%4,%5,%6,%7}, {%8,%9}, {%0,%1,%2,%3};"       \
                 : "+f"((d)[0]), "+f"((d)[1]), "+f"((d)[2]), "+f"((d)[3])      \
                 : "r"(a0), "r"(a1), "r"(a2), "r"(a3), "r"(b0), "r"(b1))

#define CP_ASYNC16(dst, src)                                                   \
    asm volatile("cp.async.cg.shared.global [%0], [%1], 16;"                   \
                 :: "r"(dst), "l"(src))
#define CP_COMMIT() asm volatile("cp.async.commit_group;" ::: "memory")
#define CP_WAIT0()  asm volatile("cp.async.wait_group 0;" ::: "memory")

// ===========================================================================
// Kernel 0: exact ||e_k||^2 (sequential mul-then-add) + ebf convert + zero loss
// ===========================================================================
__global__ void vq_prep_kernel(const float* __restrict__ emb) {
    int k = blockIdx.x * blockDim.x + threadIdx.x;
    if (k == 0) g_loss_sum = 0.0;
    if (k < KK) {
        const float* e = emb + (size_t)k * DD;
        float acc = 0.0f;
        #pragma unroll 8
        for (int d = 0; d < DD; ++d) {
            float v = e[d];
            acc = __fadd_rn(acc, __fmul_rn(v, v));
            g_ebf[(size_t)k * DD + d] = __float2bfloat16_rn(v);
        }
        g_e2[k] = acc;
    }
}

// ===========================================================================
// Kernel 1: fused transpose (zt fp32 + zbf bf16) + exact r2.
// Block: 32 tokens x full 256 d. Load [d][t] coalesced into smem; write-out
// phase: thread (tok=tid>>3, q=tid&7) handles d = jj*32 + q*4 + 0..3 ->
// 128B-coalesced float4 stores, bank-conflict-free smem reads.
// r2: 32 threads, strictly sequential ascending-d (validated R2).
// ===========================================================================
__global__ void __launch_bounds__(256) vq_convert_r2_kernel(const float* __restrict__ z) {
    __shared__ float tile[256][33];
    const int b = blockIdx.x >> 7, t0 = (blockIdx.x & 127) << 5;
    const int tid = threadIdx.x;
    const int tx = tid & 31, ty = tid >> 5;           // 32 x 8
    const float* src = z + (size_t)b * DD * TT + t0;
    #pragma unroll
    for (int k = 0; k < 32; ++k) {
        int d = ty + (k << 3);
        tile[d][tx] = src[(size_t)d * TT + tx];
    }
    __syncthreads();

    const int tok = tid >> 3, q = tid & 7;
    const size_t base = ((size_t)((b << 12) + t0 + tok)) * DD;
    #pragma unroll
    for (int jj = 0; jj < 8; ++jj) {
        int d0 = (jj << 5) + (q << 2);
        float4 v = make_float4(tile[d0][tok], tile[d0 + 1][tok],
                               tile[d0 + 2][tok], tile[d0 + 3][tok]);
        *(float4*)&g_zt[base + d0] = v;
        __nv_bfloat162 b01 = __floats2bfloat162_rn(v.x, v.y);
        __nv_bfloat162 b23 = __floats2bfloat162_rn(v.z, v.w);
        *(__nv_bfloat162*)&g_zbf[base + d0]     = b01;
        *(__nv_bfloat162*)&g_zbf[base + d0 + 2] = b23;
    }

    if (tid < 32) {
        float acc = 0.0f;
        #pragma unroll 8
        for (int d = 0; d < DD; ++d) {
            float v = tile[d][tid];
            acc = __fadd_rn(acc, __fmul_rn(v, v));
        }
        g_r2[(b << 12) + t0 + tid] = acc;
    }
}

// ===========================================================================
// Kernel 2: FUSED bf16 HMMA + in-CTA select.
// CTA = 64 tokens, 512 threads / 16 warps. 16 chunks of 64 codes, K=256.
// Warp w: rg=w&3 (16 rows), ch=w>>2 (16 cols) -- validated fragment maps.
// B single-buffered; next chunk prefetched into registers during compute,
// STS'd after the barrier (manual double-buffer through regs).
// Phase 1 epilogue: da = fl(e2 - 2*score) -> fp16 smem scores [64][1048].
// Phase 2 (after all chunks): warp-per-token (4 tokens/warp) -- the
// R7-VALIDATED select: final-min shfl reduce, margin filter (widened for
// fp16 quantization), lane-parallel exact rescore (sequential ascending-d
// fmaf, bit-matches reference), (dist, lowest-code) reduce.
// Fallback >32 candidates: exact serial full scan.
// ===========================================================================
#define A_OFF    0                     // 32768 B
#define B_OFF    32768                 // 32768 B
#define ES2_OFF  65536                 // 4096 B
#define S_OFF    69632                 // 64*1048*2 = 134144 B
#define CL_OFF   203776                // 16*34*2 = 1088 B
#define SMEM_TOT 204928
#define S_STRIDE 1048

__global__ void __launch_bounds__(512, 1) vq_mma_select_kernel(const float* __restrict__ emb) {
    extern __shared__ char smem[];
    const uint32_t sb = s2u(smem);
    const int tid = threadIdx.x, wid = tid >> 5, lane = tid & 31;
    const int tok0 = blockIdx.x << 6;

    float* es2s = (float*)(smem + ES2_OFF);
    __half* S   = (__half*)(smem + S_OFF);
    unsigned short* clist = (unsigned short*)(smem + CL_OFF);

    es2s[tid]       = g_e2[tid];
    es2s[tid + 512] = g_e2[tid + 512];

    // A tile (64 tokens x 256 d bf16, swizzled) + B chunk 0 via cp.async.
    const uint4* zsrc = (const uint4*)(g_zbf + ((size_t)tok0 << 8));
    #pragma unroll
    for (int i = tid; i < 2048; i += 512) {
        int row = i >> 5, kb = i & 31;
        CP_ASYNC16(sb + A_OFF + row * 512 + ((kb ^ (row & 7)) << 4), zsrc + i);
    }
    {
        const uint4* esrc = (const uint4*)g_ebf;
        #pragma unroll
        for (int i = tid; i < 2048; i += 512) {
            int row = i >> 5, kb = i & 31;
            CP_ASYNC16(sb + B_OFF + row * 512 + ((kb ^ (row & 7)) << 4), esrc + i);
        }
    }
    CP_COMMIT();
    CP_WAIT0();
    __syncthreads();

    // Warp tile mapping (validated lane math; m0/nb0 re-based).
    const int rg = wid & 3, ch = wid >> 2;
    const int m0 = rg << 4, nb0 = ch << 4;
    const int lr = lane & 7;
    const int arow = m0 + lr + (((lane >> 3) & 1) << 3);
    const int akc  = lane >> 4;
    const int brow = nb0 + lr + ((lane >> 4) << 3);
    const int bkc  = (lane >> 3) & 1;
    const uint32_t aBase = sb + A_OFF + (uint32_t)arow * 512;
    const uint32_t bBase = sb + B_OFF + (uint32_t)brow * 512;
    const int r0 = m0 + (lane >> 2);
    const int cb = (lane & 3) << 1;

    uint4 pre[4];
    for (int c = 0; c < 16; ++c) {
        // Prefetch next B chunk into registers (consumed after the barrier).
        if (c < 15) {
            const uint4* nsrc = (const uint4*)(g_ebf + ((size_t)((c + 1) << 6) << 8));
            #pragma unroll
            for (int j = 0; j < 4; ++j) pre[j] = __ldg(nsrc + tid + (j << 9));
        }

        float acc0[4] = {0.f, 0.f, 0.f, 0.f};
        float acc1[4] = {0.f, 0.f, 0.f, 0.f};
        #pragma unroll
        for (int s = 0; s < 16; ++s) {
            uint32_t a0, a1, a2, a3, b0, b1, b2, b3;
            LDSM_X4(a0, a1, a2, a3,
                    aBase + (uint32_t)(((2 * s + akc) ^ (arow & 7)) << 4));
            LDSM_X4(b0, b1, b2, b3,
                    bBase + (uint32_t)(((2 * s + bkc) ^ (brow & 7)) << 4));
            MMA16816(acc0, a0, a1, a2, a3, b0, b1);
            MMA16816(acc1, a0, a1, a2, a3, b2, b3);
        }

        // Epilogue: da = fl(e2 - 2*score) -> fp16 smem (conflict-free stride).
        {
            int g0 = (c << 6) + nb0 + cb;         // n8 tile 0, this thread's cols
            int g1 = g0 + 8;                      // n8 tile 1
            __half2 h00 = __floats2half2_rn(fmaf(-2.0f, acc0[0], es2s[g0 & 1023]),
                                            fmaf(-2.0f, acc0[1], es2s[(g0 + 1) & 1023]));
            __half2 h01 = __floats2half2_rn(fmaf(-2.0f, acc0[2], es2s[g0 & 1023]),
                                            fmaf(-2.0f, acc0[3], es2s[(g0 + 1) & 1023]));
            __half2 h10 = __floats2half2_rn(fmaf(-2.0f, acc1[0], es2s[g1 & 1023]),
                                            fmaf(-2.0f, acc1[1], es2s[(g1 + 1) & 1023]));
            __half2 h11 = __floats2half2_rn(fmaf(-2.0f, acc1[2], es2s[g1 & 1023]),
                                            fmaf(-2.0f, acc1[3], es2s[(g1 + 1) & 1023]));
            *(__half2*)&S[(size_t)r0 * S_STRIDE + g0]       = h00;
            *(__half2*)&S[(size_t)(r0 + 8) * S_STRIDE + g0] = h01;
            *(__half2*)&S[(size_t)r0 * S_STRIDE + g1]       = h10;
            *(__half2*)&S[(size_t)(r0 + 8) * S_STRIDE + g1] = h11;
        }
        __syncthreads();   // all warps done with current B + scores written
        if (c < 15) {
            #pragma unroll
            for (int j = 0; j < 4; ++j) {
                int lin = tid + (j << 9);
                int row = lin >> 5, kb = lin & 31;
                *(uint4*)(smem + B_OFF + row * 512 + ((kb ^ (row & 7)) << 4)) = pre[j];
            }
            __syncthreads();
        }
    }

    // ---------------- Phase 2: warp-per-token select (R7-validated) --------
    for (int it = 0; it < 4; ++it) {
        const int tl = (wid << 2) + it;
        const int tok = tok0 + tl;
        const __half* row = S + (size_t)tl * S_STRIDE;

        float4 v[8];
        float mn = CUDART_INF_F;
        #pragma unroll
        for (int i = 0; i < 8; ++i) {
            uint2 h = *(const uint2*)(row + (i << 7) + (lane << 2));
            float2 f01 = __half22float2(((const __half2*)&h)[0]);
            float2 f23 = __half22float2(((const __half2*)&h)[1]);
            v[i] = make_float4(f01.x, f01.y, f23.x, f23.y);
            mn = fminf(mn, fminf(fminf(v[i].x, v[i].y), fminf(v[i].z, v[i].w)));
        }
        #pragma unroll
        for (int off = 16; off > 0; off >>= 1)
            mn = fminf(mn, __shfl_xor_sync(0xffffffffu, mn, off));

        const float r2 = g_r2[tok];
        // margin = 2B + 2*fp16_quant: B = 2^-6*1.01*||z||*||e||max + eps.
        const float thr = mn + fmaf(0.0325f * 0.015625f, sqrtf(r2), 7e-4f);

        int cnt = 0;
        #pragma unroll
        for (int i = 0; i < 8; ++i)
            cnt += (v[i].x <= thr) + (v[i].y <= thr) + (v[i].z <= thr) + (v[i].w <= thr);
        int off = cnt;
        #pragma unroll
        for (int d = 1; d < 32; d <<= 1) {
            int t2 = __shfl_up_sync(0xffffffffu, off, d);
            if (lane >= d) off += t2;
        }
        const int total = __shfl_sync(0xffffffffu, off, 31);
        const int excl = off - cnt;

        const float* zr = g_zt + (size_t)tok * DD;
        int bc = 0;

        if (total <= 32) {
            int k = excl;
            unsigned short* cl = clist + wid * 34;
            #pragma unroll
            for (int i = 0; i < 8; ++i) {
                int base = (i << 7) + (lane << 2);
                if (v[i].x <= thr) cl[k++] = (unsigned short)(base + 0);
                if (v[i].y <= thr) cl[k++] = (unsigned short)(base + 1);
                if (v[i].z <= thr) cl[k++] = (unsigned short)(base + 2);
                if (v[i].w <= thr) cl[k++] = (unsigned short)(base + 3);
            }
            __syncwarp();
            float bd = CUDART_INF_F;
            bc = 0x7fffffff;
            if (lane < total) {
                int code = cl[lane];
                const float* er = emb + ((size_t)code << 8);
                float acc = 0.0f;
                #pragma unroll 8
                for (int d = 0; d < DD; ++d)
                    acc = fmaf(zr[d], __ldg(&er[d]), acc);
                bd = __fsub_rn(__fadd_rn(r2, es2s[code]), __fmul_rn(2.0f, acc));
                bc = code;
            }
            #pragma unroll
            for (int d = 16; d > 0; d >>= 1) {
                float od = __shfl_xor_sync(0xffffffffu, bd, d);
                int   oc = __shfl_xor_sync(0xffffffffu, bc, d);
                if (od < bd || (od == bd && oc < bc)) { bd = od; bc = oc; }
            }
            __syncwarp();
        } else if (lane == 0) {
            float bd = CUDART_INF_F;
            bc = 0;
            for (int code = 0; code < KK; ++code) {
                const float* er = emb + ((size_t)code << 8);
                float acc = 0.0f;
                #pragma unroll 8
                for (int d = 0; d < DD; ++d)
                    acc = fmaf(zr[d], __ldg(&er[d]), acc);
                float dist = __fsub_rn(__fadd_rn(r2, es2s[code]),
                                       __fmul_rn(2.0f, acc));
                if (dist < bd) { bd = dist; bc = code; }
            }
        }
        if (lane == 0) g_idx[tok] = bc;
    }
}

// ===========================================================================
// Kernel 3: gather + straight-through output + loss partial sums (float4).
// out[b,d,t] = fl(z + fl(q - z)); loss terms fl((q-z)^2) in double.
// ===========================================================================
__global__ void vq_output_kernel(const float* __restrict__ z,
                                 const float* __restrict__ emb,
                                 float* __restrict__ out) {
    double local = 0.0;
    const size_t nvec = NDATA >> 2;
    const size_t stride = (size_t)gridDim.x * blockDim.x;
    for (size_t i = (size_t)blockIdx.x * blockDim.x + threadIdx.x; i < nvec; i += stride) {
        size_t e = i << 2;
        int t  = (int)(e & 4095);
        int d  = (int)((e >> 12) & 255);
        int bb = (int)(e >> 20);
        int4 idx = *(const int4*)&g_idx[(bb << 12) + t];
        float4 zv = *(const float4*)&z[e];
        float q0 = __ldg(&emb[((size_t)idx.x << 8) + d]);
        float q1 = __ldg(&emb[((size_t)idx.y << 8) + d]);
        float q2 = __ldg(&emb[((size_t)idx.z << 8) + d]);
        float q3 = __ldg(&emb[((size_t)idx.w << 8) + d]);
        float d0 = __fsub_rn(q0, zv.x), d1 = __fsub_rn(q1, zv.y);
        float d2 = __fsub_rn(q2, zv.z), d3 = __fsub_rn(q3, zv.w);
        float4 ov = make_float4(__fadd_rn(zv.x, d0), __fadd_rn(zv.y, d1),
                                __fadd_rn(zv.z, d2), __fadd_rn(zv.w, d3));
        *(float4*)&out[e] = ov;
        local += (double)__fmul_rn(d0, d0) + (double)__fmul_rn(d1, d1)
               + (double)__fmul_rn(d2, d2) + (double)__fmul_rn(d3, d3);
    }
    #pragma unroll
    for (int off = 16; off > 0; off >>= 1)
        local += __shfl_down_sync(0xffffffffu, local, off);
    __shared__ double wsum[8];
    int lane = threadIdx.x & 31, wid = threadIdx.x >> 5;
    if (lane == 0) wsum[wid] = local;
    __syncthreads();
    if (threadIdx.x == 0) {
        double s = 0.0;
        #pragma unroll
        for (int i = 0; i < 8; ++i) s += wsum[i];
        atomicAdd(&g_loss_sum, s);
    }
}

// ===========================================================================
// Kernel 4: finalize loss = fl(m + fl(0.25*m)).
// ===========================================================================
__global__ void vq_finalize_kernel(float* __restrict__ out, int out_size) {
    if (threadIdx.x == 0 && blockIdx.x == 0) {
        if ((size_t)out_size > NDATA) {
            float m = (float)(g_loss_sum * (1.0 / 16777216.0));
            out[NDATA] = __fadd_rn(m, __fmul_rn(0.25f, m));
        }
    }
}

// ===========================================================================
extern "C" void kernel_launch(void* const* d_in, const int* in_sizes, int n_in,
                              void* d_out, int out_size) {
    const float* z   = (const float*)d_in[0];
    const float* emb = (const float*)d_in[1];
    if (n_in >= 2 && in_sizes[0] == KK * DD && (size_t)in_sizes[1] == NDATA) {
        const float* tmp = z; z = emb; emb = tmp;
    }
    float* out = (float*)d_out;

    cudaFuncSetAttribute((const void*)vq_mma_select_kernel,
                         cudaFuncAttributeMaxDynamicSharedMemorySize, SMEM_TOT);

    vq_prep_kernel<<<4, 256>>>(emb);
    vq_convert_r2_kernel<<<NTOK / 32, 256>>>(z);
    vq_mma_select_kernel<<<NTOK / 64, 512, SMEM_TOT>>>(emb);
    vq_output_kernel<<<2048, 256>>>(z, emb, out);
    vq_finalize_kernel<<<1, 32>>>(out, out_size);
}

// round 10
// speedup vs baseline: 1.0056x; 1.0056x over previous
#include <cuda_runtime.h>
#include <cuda_bf16.h>
#include <cuda_fp16.h>
#include <math_constants.h>
#include <cstdint>

// Problem constants
#define DD 256
#define TT 4096
#define BBATCH 16
#define KK 1024
#define NTOK (BBATCH * TT)                  // 65536 tokens
#define NDATA ((size_t)BBATCH * DD * TT)    // 16777216 output data elements

// Scratch (no cudaMalloc allowed)
__device__ float          g_e2[KK];
__device__ float          g_r2[NTOK];
__device__ int            g_idx[NTOK];
__device__ double         g_loss_sum;
__device__ float          g_zt[NDATA];          // z transposed [token][d] fp32
__device__ __nv_bfloat16  g_zbf[NDATA];         // z transposed bf16
__device__ __nv_bfloat16  g_ebf[KK * DD];       // emb bf16
__device__ __half         g_dah[(size_t)NTOK * KK];  // approx dists fp16 (128 MB)

__device__ __forceinline__ uint32_t s2u(const void* p) {
    uint32_t a;
    asm("{ .reg .u64 t; cvta.to.shared.u64 t, %1; cvt.u32.u64 %0, t; }"
        : "=r"(a) : "l"(p));
    return a;
}

#define LDSM_X4(r0, r1, r2, r3, addr)                                          \
    asm volatile("ldmatrix.sync.aligned.m8n8.x4.shared.b16 {%0,%1,%2,%3}, [%4];" \
                 : "=r"(r0), "=r"(r1), "=r"(r2), "=r"(r3) : "r"(addr))

#define MMA16816(d, a0, a1, a2, a3, b0, b1)                                    \
    asm volatile("mma.sync.aligned.m16n8k16.row.col.f32.bf16.bf16.f32 "        \
                 "{%0,%1,%2,%3}, {%4,%5,%6,%7}, {%8,%9}, {%0,%1,%2,%3};"       \
                 : "+f"((d)[0]), "+f"((d)[1]), "+f"((d)[2]), "+f"((d)[3])      \
                 : "r"(a0), "r"(a1), "r"(a2), "r"(a3), "r"(b0), "r"(b1))

#define CP_ASYNC16(dst, src)                                                   \
    asm volatile("cp.async.cg.shared.global [%0], [%1], 16;"                   \
                 :: "r"(dst), "l"(src))
#define CP_COMMIT() asm volatile("cp.async.commit_group;" ::: "memory")
#define CP_WAIT0()  asm volatile("cp.async.wait_group 0;" ::: "memory")

// ===========================================================================
// Kernel 0: exact ||e_k||^2 (sequential mul-then-add) + ebf convert + zero loss
// ===========================================================================
__global__ void vq_prep_kernel(const float* __restrict__ emb) {
    int k = blockIdx.x * blockDim.x + threadIdx.x;
    if (k == 0) g_loss_sum = 0.0;
    if (k < KK) {
        const float* e = emb + (size_t)k * DD;
        float acc = 0.0f;
        #pragma unroll 8
        for (int d = 0; d < DD; ++d) {
            float v = e[d];
            acc = __fadd_rn(acc, __fmul_rn(v, v));
            g_ebf[(size_t)k * DD + d] = __float2bfloat16_rn(v);
        }
        g_e2[k] = acc;
    }
}

// ===========================================================================
// Kernel 1: fused transpose (zt fp32 + zbf bf16) + exact r2 (validated R9).
// ===========================================================================
__global__ void __launch_bounds__(256) vq_convert_r2_kernel(const float* __restrict__ z) {
    __shared__ float tile[256][33];
    const int b = blockIdx.x >> 7, t0 = (blockIdx.x & 127) << 5;
    const int tid = threadIdx.x;
    const int tx = tid & 31, ty = tid >> 5;           // 32 x 8
    const float* src = z + (size_t)b * DD * TT + t0;
    #pragma unroll
    for (int k = 0; k < 32; ++k) {
        int d = ty + (k << 3);
        tile[d][tx] = src[(size_t)d * TT + tx];
    }
    __syncthreads();

    const int tok = tid >> 3, q = tid & 7;
    const size_t base = ((size_t)((b << 12) + t0 + tok)) * DD;
    #pragma unroll
    for (int jj = 0; jj < 8; ++jj) {
        int d0 = (jj << 5) + (q << 2);
        float4 v = make_float4(tile[d0][tok], tile[d0 + 1][tok],
                               tile[d0 + 2][tok], tile[d0 + 3][tok]);
        *(float4*)&g_zt[base + d0] = v;
        __nv_bfloat162 b01 = __floats2bfloat162_rn(v.x, v.y);
        __nv_bfloat162 b23 = __floats2bfloat162_rn(v.z, v.w);
        *(__nv_bfloat162*)&g_zbf[base + d0]     = b01;
        *(__nv_bfloat162*)&g_zbf[base + d0 + 2] = b23;
    }

    if (tid < 32) {
        float acc = 0.0f;
        #pragma unroll 8
        for (int d = 0; d < DD; ++d) {
            float v = tile[d][tid];
            acc = __fadd_rn(acc, __fmul_rn(v, v));
        }
        g_r2[(b << 12) + t0 + tid] = acc;
    }
}

// ===========================================================================
// Kernel 2: bf16 HMMA approx-dist GEMM -- EXACT R7 structure (227us, 122
// regs, validated), only the epilogue changed: da stored as fp16 (halves the
// write traffic that bounded R7). 512 threads / 16 warps; warp w: rows
// rg=w&7 (16 tokens), col half ch=w>>3. cp.async double-buffered B.
// ===========================================================================
#define ES2_OFF 0                      // 4096 B
#define A_OFF   4096                   // 65536 B
#define B0_OFF  69632                  // 65536 B
#define B1_OFF  135168                 // 65536 B
#define SMEM_TOT 200704

__global__ void __launch_bounds__(512, 1) vq_mma_kernel() {
    extern __shared__ char smem[];
    const uint32_t sb = s2u(smem);
    const int tid = threadIdx.x, wid = tid >> 5, lane = tid & 31;
    const int tok0 = blockIdx.x << 7;
    float* es2s = (float*)(smem + ES2_OFF);

    es2s[tid]       = g_e2[tid];
    es2s[tid + 512] = g_e2[tid + 512];

    const uint4* zsrc = (const uint4*)(g_zbf + ((size_t)tok0 << 8));
    #pragma unroll 2
    for (int i = tid; i < 4096; i += 512) {
        int row = i >> 5, kb = i & 31;
        CP_ASYNC16(sb + A_OFF + row * 512 + ((kb ^ (row & 7)) << 4), zsrc + i);
    }
    {
        const uint4* esrc = (const uint4*)g_ebf;
        #pragma unroll 2
        for (int i = tid; i < 4096; i += 512) {
            int row = i >> 5, kb = i & 31;
            CP_ASYNC16(sb + B0_OFF + row * 512 + ((kb ^ (row & 7)) << 4), esrc + i);
        }
    }
    CP_COMMIT();
    CP_WAIT0();
    __syncthreads();

    // Warp tile mapping (validated R6/R7).
    const int rg = wid & 7, ch = wid >> 3;
    const int m0 = rg << 4, nb0 = ch << 6;
    const int lr = lane & 7;
    const int arow = m0 + lr + (((lane >> 3) & 1) << 3);
    const int akc  = lane >> 4;
    const int brow_off = lr + ((lane >> 4) << 3);
    const int bkc  = (lane >> 3) & 1;
    const uint32_t aBase = sb + A_OFF + (uint32_t)arow * 512;

    for (int c = 0; c < 8; ++c) {
        const int nc0 = c << 7;
        const uint32_t bOff = (c & 1) ? B1_OFF : B0_OFF;

        if (c < 7) {
            const uint32_t nOff = (c & 1) ? B0_OFF : B1_OFF;
            const uint4* esrc = (const uint4*)(g_ebf + ((size_t)(nc0 + 128) << 8));
            #pragma unroll 2
            for (int i = tid; i < 4096; i += 512) {
                int row = i >> 5, kb = i & 31;
                CP_ASYNC16(sb + nOff + row * 512 + ((kb ^ (row & 7)) << 4), esrc + i);
            }
            CP_COMMIT();
        }

        float acc[8][4];
        #pragma unroll
        for (int nt = 0; nt < 8; ++nt)
            #pragma unroll
            for (int q = 0; q < 4; ++q) acc[nt][q] = 0.0f;

        #pragma unroll
        for (int s = 0; s < 16; ++s) {
            uint32_t a0, a1, a2, a3;
            int ach = 2 * s + akc;
            LDSM_X4(a0, a1, a2, a3, aBase + (uint32_t)((ach ^ (arow & 7)) << 4));
            #pragma unroll
            for (int p = 0; p < 4; ++p) {
                int brow = nb0 + (p << 4) + brow_off;
                int bch  = 2 * s + bkc;
                uint32_t b0, b1, b2, b3;
                LDSM_X4(b0, b1, b2, b3,
                        sb + bOff + (uint32_t)brow * 512
                                  + (uint32_t)((bch ^ (brow & 7)) << 4));
                MMA16816(acc[2 * p],     a0, a1, a2, a3, b0, b1);
                MMA16816(acc[2 * p + 1], a0, a1, a2, a3, b2, b3);
            }
        }

        // Epilogue: da = fl(e2 - 2*score) -> fp16, __half2 stores.
        // fp16 quantization is absorbed by the select margin (validated R9).
        {
            int r0 = tok0 + m0 + (lane >> 2);
            int cb = (lane & 3) << 1;
            #pragma unroll
            for (int nt = 0; nt < 8; ++nt) {
                int col = nb0 + (nt << 3) + cb;       // 0..127, even
                float e20 = es2s[nc0 + col];
                float e21 = es2s[nc0 + col + 1];
                __half2 v0 = __floats2half2_rn(fmaf(-2.0f, acc[nt][0], e20),
                                               fmaf(-2.0f, acc[nt][1], e21));
                __half2 v1 = __floats2half2_rn(fmaf(-2.0f, acc[nt][2], e20),
                                               fmaf(-2.0f, acc[nt][3], e21));
                *(__half2*)&g_dah[(size_t)r0 * KK + nc0 + col]       = v0;
                *(__half2*)&g_dah[(size_t)(r0 + 8) * KK + nc0 + col] = v1;
            }
        }

        if (c < 7) {
            CP_WAIT0();
            __syncthreads();
        }
    }
}

// ===========================================================================
// Kernel 3: warp-per-token select + exact rescore (logic validated R7/R9),
// reading fp16 approx dists. Final-min shfl reduce, margin filter (incl.
// fp16 quantization, validated R9), lane-parallel exact rescore (sequential
// ascending-d fmaf, bit-matches reference), (dist, lowest-code) reduce.
// Fallback >32 candidates: exact serial full scan.
// ===========================================================================
__global__ void __launch_bounds__(256) vq_select_kernel(const float* __restrict__ emb) {
    const int warp = threadIdx.x >> 5, lane = threadIdx.x & 31;
    const int tok = (blockIdx.x << 3) + warp;
    const __half* da = g_dah + (size_t)tok * KK;

    float4 v[8];
    float mn = CUDART_INF_F;
    #pragma unroll
    for (int i = 0; i < 8; ++i) {
        uint2 h = *(const uint2*)(da + (i << 7) + (lane << 2));
        float2 f01 = __half22float2(((const __half2*)&h)[0]);
        float2 f23 = __half22float2(((const __half2*)&h)[1]);
        v[i] = make_float4(f01.x, f01.y, f23.x, f23.y);
        mn = fminf(mn, fminf(fminf(v[i].x, v[i].y), fminf(v[i].z, v[i].w)));
    }
    #pragma unroll
    for (int off = 16; off > 0; off >>= 1)
        mn = fminf(mn, __shfl_xor_sync(0xffffffffu, mn, off));

    const float r2 = g_r2[tok];
    // margin = 2B + 2*fp16_quant; B = 2^-6*1.01*||z||*||e||max + eps.
    const float thr = mn + fmaf(0.0325f * 0.015625f, sqrtf(r2), 7e-4f);

    int cnt = 0;
    #pragma unroll
    for (int i = 0; i < 8; ++i)
        cnt += (v[i].x <= thr) + (v[i].y <= thr) + (v[i].z <= thr) + (v[i].w <= thr);
    int off = cnt;
    #pragma unroll
    for (int d = 1; d < 32; d <<= 1) {
        int t2 = __shfl_up_sync(0xffffffffu, off, d);
        if (lane >= d) off += t2;
    }
    const int total = __shfl_sync(0xffffffffu, off, 31);
    const int excl = off - cnt;

    __shared__ unsigned short clist[8][36];
    const float* zr = g_zt + (size_t)tok * DD;
    int bc = 0;

    if (total <= 32) {
        int k = excl;
        #pragma unroll
        for (int i = 0; i < 8; ++i) {
            int base = (i << 7) + (lane << 2);
            if (v[i].x <= thr) clist[warp][k++] = (unsigned short)(base + 0);
            if (v[i].y <= thr) clist[warp][k++] = (unsigned short)(base + 1);
            if (v[i].z <= thr) clist[warp][k++] = (unsigned short)(base + 2);
            if (v[i].w <= thr) clist[warp][k++] = (unsigned short)(base + 3);
        }
        __syncwarp();
        float bd = CUDART_INF_F;
        bc = 0x7fffffff;
        if (lane < total) {
            int code = clist[warp][lane];
            const float* er = emb + ((size_t)code << 8);
            float acc = 0.0f;
            #pragma unroll 8
            for (int d = 0; d < DD; ++d)
                acc = fmaf(zr[d], __ldg(&er[d]), acc);
            bd = __fsub_rn(__fadd_rn(r2, g_e2[code]), __fmul_rn(2.0f, acc));
            bc = code;
        }
        #pragma unroll
        for (int d = 16; d > 0; d >>= 1) {
            float od = __shfl_xor_sync(0xffffffffu, bd, d);
            int   oc = __shfl_xor_sync(0xffffffffu, bc, d);
            if (od < bd || (od == bd && oc < bc)) { bd = od; bc = oc; }
        }
    } else if (lane == 0) {
        float bd = CUDART_INF_F;
        bc = 0;
        for (int code = 0; code < KK; ++code) {
            const float* er = emb + ((size_t)code << 8);
            float acc = 0.0f;
            #pragma unroll 8
            for (int d = 0; d < DD; ++d)
                acc = fmaf(zr[d], __ldg(&er[d]), acc);
            float dist = __fsub_rn(__fadd_rn(r2, g_e2[code]),
                                   __fmul_rn(2.0f, acc));
            if (dist < bd) { bd = dist; bc = code; }
        }
    }
    if (lane == 0) g_idx[tok] = bc;
}

// ===========================================================================
// Kernel 4: gather + straight-through output + loss partial sums (float4,
// validated R9: 78us). out = fl(z + fl(q - z)); loss fl((q-z)^2) in double.
// ===========================================================================
__global__ void vq_output_kernel(const float* __restrict__ z,
                                 const float* __restrict__ emb,
                                 float* __restrict__ out) {
    double local = 0.0;
    const size_t nvec = NDATA >> 2;
    const size_t stride = (size_t)gridDim.x * blockDim.x;
    for (size_t i = (size_t)blockIdx.x * blockDim.x + threadIdx.x; i < nvec; i += stride) {
        size_t e = i << 2;
        int t  = (int)(e & 4095);
        int d  = (int)((e >> 12) & 255);
        int bb = (int)(e >> 20);
        int4 idx = *(const int4*)&g_idx[(bb << 12) + t];
        float4 zv = *(const float4*)&z[e];
        float q0 = __ldg(&emb[((size_t)idx.x << 8) + d]);
        float q1 = __ldg(&emb[((size_t)idx.y << 8) + d]);
        float q2 = __ldg(&emb[((size_t)idx.z << 8) + d]);
        float q3 = __ldg(&emb[((size_t)idx.w << 8) + d]);
        float d0 = __fsub_rn(q0, zv.x), d1 = __fsub_rn(q1, zv.y);
        float d2 = __fsub_rn(q2, zv.z), d3 = __fsub_rn(q3, zv.w);
        float4 ov = make_float4(__fadd_rn(zv.x, d0), __fadd_rn(zv.y, d1),
                                __fadd_rn(zv.z, d2), __fadd_rn(zv.w, d3));
        *(float4*)&out[e] = ov;
        local += (double)__fmul_rn(d0, d0) + (double)__fmul_rn(d1, d1)
               + (double)__fmul_rn(d2, d2) + (double)__fmul_rn(d3, d3);
    }
    #pragma unroll
    for (int off = 16; off > 0; off >>= 1)
        local += __shfl_down_sync(0xffffffffu, local, off);
    __shared__ double wsum[8];
    int lane = threadIdx.x & 31, wid = threadIdx.x >> 5;
    if (lane == 0) wsum[wid] = local;
    __syncthreads();
    if (threadIdx.x == 0) {
        double s = 0.0;
        #pragma unroll
        for (int i = 0; i < 8; ++i) s += wsum[i];
        atomicAdd(&g_loss_sum, s);
    }
}

// ===========================================================================
// Kernel 5: finalize loss = fl(m + fl(0.25*m)).
// ===========================================================================
__global__ void vq_finalize_kernel(float* __restrict__ out, int out_size) {
    if (threadIdx.x == 0 && blockIdx.x == 0) {
        if ((size_t)out_size > NDATA) {
            float m = (float)(g_loss_sum * (1.0 / 16777216.0));
            out[NDATA] = __fadd_rn(m, __fmul_rn(0.25f, m));
        }
    }
}

// ===========================================================================
extern "C" void kernel_launch(void* const* d_in, const int* in_sizes, int n_in,
                              void* d_out, int out_size) {
    const float* z   = (const float*)d_in[0];
    const float* emb = (const float*)d_in[1];
    if (n_in >= 2 && in_sizes[0] == KK * DD && (size_t)in_sizes[1] == NDATA) {
        const float* tmp = z; z = emb; emb = tmp;
    }
    float* out = (float*)d_out;

    cudaFuncSetAttribute((const void*)vq_mma_kernel,
                         cudaFuncAttributeMaxDynamicSharedMemorySize, SMEM_TOT);

    vq_prep_kernel<<<4, 256>>>(emb);
    vq_convert_r2_kernel<<<NTOK / 32, 256>>>(z);
    vq_mma_kernel<<<NTOK / 128, 512, SMEM_TOT>>>();
    vq_select_kernel<<<NTOK / 8, 256>>>(emb);
    vq_output_kernel<<<2048, 256>>>(z, emb, out);
    vq_finalize_kernel<<<1, 32>>>(out, out_size);
}